// round 7
// baseline (speedup 1.0000x reference)
#include <cuda_runtime.h>

#define BB 32
#define NN 2048
#define HH 512
#define NCH 16           // n-chunks per batch for the fused pass
#define NPC (NN/NCH)     // 128 rows per chunk
#define TO 4             // o-rows per k_out block

// ---- scratch (device globals; no allocation allowed) ----
__device__ float g_p[BB*NN];              // unnormalized exp weights
__device__ float g_psum[BB*NCH];          // partial sums of p
__device__ float g_upart[BB*NCH*2*HH];    // partial weighted-V sums
__device__ float g_u[BB*2*HH];            // normalized u0|u1

__device__ __forceinline__ float warp_sum(float v) {
#pragma unroll
    for (int o = 16; o; o >>= 1) v += __shfl_xor_sync(0xffffffffu, v, o);
    return v;
}

// ---------------- fused: qdot, alpha -> p = adj*exp(alpha), weighted V partials ----------------
// EXACT round-3 configuration (measured 49.7us @ 69.7% DRAM): grid (NCH, BB),
// 512 threads, no launch_bounds, smem phase-2 reduction.
// No max-subtraction needed: alpha ~ N(0,~0.8) => max over 64k ~ 3.5; exp safe.
__global__ void k_fused(const float* __restrict__ Q,
                        const float* __restrict__ K,
                        const float* __restrict__ V,
                        const float* __restrict__ w_att,
                        const float* __restrict__ b_att,
                        const int*   __restrict__ adj,
                        const int*   __restrict__ s_mask) {
    __shared__ float wk[HH];
    __shared__ float sw0[NPC], sw1[NPC];
    __shared__ float sred[16];
    __shared__ float s_qd;
    __shared__ float4 red0[512], red1[512];

    int b = blockIdx.y, c = blockIdx.x;
    int n0 = c * NPC;
    int t = threadIdx.x;
    int w = t >> 5, l = t & 31;

    for (int i = t; i < HH; i += 512) wk[i] = w_att[HH + i];

    // ---- phase 0: qdot for this b ----
    float qv = Q[b * HH + t] * w_att[t];
    qv = warp_sum(qv);
    if (l == 0) sred[w] = qv;
    __syncthreads();
    if (t == 0) {
        float s = 0.f;
#pragma unroll
        for (int i = 0; i < 16; i++) s += sred[i];
        s_qd = s + b_att[0];
    }
    __syncthreads();

    // ---- phase 1: p for 128 rows ----
    float qd = s_qd;
    const float4* wk4 = (const float4*)wk;
#pragma unroll
    for (int j = 0; j < NPC / 16; j++) {              // 8 rows per warp
        int r = w * (NPC / 16) + j;
        const float4* kp = (const float4*)(K + ((size_t)b * NN + n0 + r) * HH);
        float s = 0.f;
#pragma unroll
        for (int i = 0; i < 4; i++) {
            float4 kv = kp[i * 32 + l];
            float4 wv = wk4[i * 32 + l];
            s += kv.x * wv.x + kv.y * wv.y + kv.z * wv.z + kv.w * wv.w;
        }
        s = warp_sum(s);
        if (l == 0) {
            int gi = b * NN + n0 + r;
            float p = adj[gi] ? __expf(s + qd) : 0.f;
            int smv = s_mask[gi];
            sw0[r] = smv ? p : 0.f;
            sw1[r] = smv ? 0.f : p;
            g_p[gi] = p;
        }
    }
    __syncthreads();

    // partial psum (warp 0; overlaps with start of phase 2 on other warps)
    if (w == 0) {
        float ps = 0.f;
#pragma unroll
        for (int i = 0; i < NPC / 32; i++) ps += sw0[i * 32 + l] + sw1[i * 32 + l];
        ps = warp_sum(ps);
        if (l == 0) g_psum[b * NCH + c] = ps;
    }

    // ---- phase 2: weighted V accumulation (float4, 4-way row split) ----
    int h4 = t & 127;                                  // float4 column 0..127
    int rg = t >> 7;                                   // row group 0..3
    const float4* vp = (const float4*)V + ((size_t)b * NN + n0 + rg * (NPC / 4)) * (HH / 4) + h4;
    float4 a0 = make_float4(0.f, 0.f, 0.f, 0.f);
    float4 a1 = make_float4(0.f, 0.f, 0.f, 0.f);
#pragma unroll 8
    for (int i = 0; i < NPC / 4; i++) {               // 32 rows
        float4 v = __ldg(vp + (size_t)i * (HH / 4));
        float x0 = sw0[rg * (NPC / 4) + i];
        float x1 = sw1[rg * (NPC / 4) + i];
        a0.x += x0 * v.x; a0.y += x0 * v.y; a0.z += x0 * v.z; a0.w += x0 * v.w;
        a1.x += x1 * v.x; a1.y += x1 * v.y; a1.z += x1 * v.z; a1.w += x1 * v.w;
    }
    red0[t] = a0;
    red1[t] = a1;
    __syncthreads();
    if (t < 128) {
        float4 r0 = red0[t], r1 = red1[t];
#pragma unroll
        for (int g = 1; g < 4; g++) {
            float4 x = red0[t + g * 128];
            r0.x += x.x; r0.y += x.y; r0.z += x.z; r0.w += x.w;
            float4 y = red1[t + g * 128];
            r1.x += y.x; r1.y += y.y; r1.z += y.z; r1.w += y.w;
        }
        float4* up0 = (float4*)(g_upart + ((size_t)(b * NCH + c) * 2 + 0) * HH);
        float4* up1 = (float4*)(g_upart + ((size_t)(b * NCH + c) * 2 + 1) * HH);
        up0[t] = r0;
        up1[t] = r1;
    }
}

// ---------------- normalize: u = sum(upart)/sum(p); attn = p/sum(p) ----------------
__global__ void k_norm(float* __restrict__ out) {
    __shared__ float pp[NCH];
    __shared__ float sinv;
    int b = blockIdx.x, t = threadIdx.x;              // 1024 threads = 2*HH values
    if (t < NCH) pp[t] = g_psum[b * NCH + t];
    __syncthreads();
    if (t == 0) {
        float s = 0.f;
#pragma unroll
        for (int i = 0; i < NCH; i++) s += pp[i];
        sinv = 1.0f / s;
    }
    __syncthreads();
    float inv = sinv;
    // reduce u partials (layout [b*NCH+c][2*HH], t indexes 2*HH)
    float s = 0.f;
#pragma unroll
    for (int cc = 0; cc < NCH; cc++)
        s += g_upart[(size_t)(b * NCH + cc) * 2 * HH + t];
    g_u[b * 2 * HH + t] = s * inv;
    // attn output
    out[b * NN + t]        = g_p[b * NN + t] * inv;
    out[b * NN + t + 1024] = g_p[b * NN + t + 1024] * inv;
}

// ---------------- epilogue: attn_sum[b,o] = u0·Wr0[o] + u1·Wr1[o] + Q[b]·Wri[o] ----------------
// grid (128 o-tiles, 2 b-halves), 256 threads. Weights in smem (24KB/block);
// warp covers 2 b values with u/Q in registers. Weight DRAM traffic: once.
__global__ void __launch_bounds__(256)
k_out(const float* __restrict__ Q,
      const float* __restrict__ Wr0,
      const float* __restrict__ Wr1,
      const float* __restrict__ Wri,
      float* __restrict__ out) {
    __shared__ float s_w[3][TO][HH];
    int o0 = blockIdx.x * TO;
    int bh = blockIdx.y;
    int t = threadIdx.x, w = t >> 5, l = t & 31;

    const float4* w0g = (const float4*)(Wr0 + (size_t)o0 * HH);
    const float4* w1g = (const float4*)(Wr1 + (size_t)o0 * HH);
    const float4* wig = (const float4*)(Wri + (size_t)o0 * HH);
#pragma unroll
    for (int i = 0; i < (TO * HH / 4) / 256; i++) {
        int idx = i * 256 + t;
        ((float4*)&s_w[0][0][0])[idx] = w0g[idx];
        ((float4*)&s_w[1][0][0])[idx] = w1g[idx];
        ((float4*)&s_w[2][0][0])[idx] = wig[idx];
    }
    __syncthreads();

#pragma unroll
    for (int bb = 0; bb < 2; bb++) {
        int b = bh * 16 + bb * 8 + w;
        const float4* u0 = (const float4*)(g_u + b * 2 * HH);
        const float4* u1 = u0 + HH / 4;
        const float4* q  = (const float4*)(Q + b * HH);
        float4 u0f[4], u1f[4], qf[4];
#pragma unroll
        for (int i = 0; i < 4; i++) {
            u0f[i] = u0[i * 32 + l];
            u1f[i] = u1[i * 32 + l];
            qf[i]  = q[i * 32 + l];
        }
#pragma unroll
        for (int o = 0; o < TO; o++) {
            const float4* sw0p = (const float4*)&s_w[0][o][0];
            const float4* sw1p = (const float4*)&s_w[1][o][0];
            const float4* swip = (const float4*)&s_w[2][o][0];
            float s = 0.f;
#pragma unroll
            for (int i = 0; i < 4; i++) {
                int idx = i * 32 + l;
                float4 x;
                x = sw0p[idx];
                s += u0f[i].x * x.x + u0f[i].y * x.y + u0f[i].z * x.z + u0f[i].w * x.w;
                x = sw1p[idx];
                s += u1f[i].x * x.x + u1f[i].y * x.y + u1f[i].z * x.z + u1f[i].w * x.w;
                x = swip[idx];
                s += qf[i].x * x.x + qf[i].y * x.y + qf[i].z * x.z + qf[i].w * x.w;
            }
            s = warp_sum(s);
            if (l == 0) out[BB * NN + b * HH + o0 + o] = s;
        }
    }
}

// ---------------- launch ----------------
extern "C" void kernel_launch(void* const* d_in, const int* in_sizes, int n_in,
                              void* d_out, int out_size) {
    const float* Q     = (const float*)d_in[0];
    const float* K     = (const float*)d_in[1];
    const float* V     = (const float*)d_in[2];
    const int*   adj   = (const int*)d_in[3];
    const int*   smask = (const int*)d_in[4];
    const float* w_att = (const float*)d_in[5];
    const float* b_att = (const float*)d_in[6];
    const float* Wr0   = (const float*)d_in[7];
    const float* Wr1   = (const float*)d_in[8];
    const float* Wri   = (const float*)d_in[9];
    float* out = (float*)d_out;

    k_fused<<<dim3(NCH, BB), 512>>>(Q, K, V, w_att, b_att, adj, smask);
    k_norm<<<BB, 1024>>>(out);
    k_out<<<dim3(HH / TO, 2), 256>>>(Q, Wr0, Wr1, Wri, out);
}

// round 8
// speedup vs baseline: 1.0771x; 1.0771x over previous
#include <cuda_runtime.h>

#define BB 32
#define NN 2048
#define HH 512
#define NCH 16           // n-chunks per batch for the fused pass
#define NPC (NN/NCH)     // 128 rows per chunk
#define RPW (NPC/16)     // rows per warp in phase 1 = 8
#define TO 4             // o-rows per k_out block

// ---- scratch (device globals; no allocation allowed) ----
__device__ float g_p[BB*NN];              // unnormalized exp weights
__device__ float g_psum[BB*NCH];          // partial sums of p
__device__ float g_upart[BB*NCH*2*HH];    // partial weighted-V sums
__device__ float g_u[BB*2*HH];            // normalized u0|u1

__device__ __forceinline__ float warp_sum(float v) {
#pragma unroll
    for (int o = 16; o; o >>= 1) v += __shfl_xor_sync(0xffffffffu, v, o);
    return v;
}

// ---------------- fused: qdot, alpha -> p = adj*exp(alpha), weighted V partials ----------------
// Round-3 geometry (grid (NCH,BB), 512 thr, smem phase-2 reduction) + phase-1
// restructure: wk in registers, 8 independent dot chains (front-batched loads),
// shuffle reductions batched at the end. launch_bounds(512,2) = reg cap 64,
// occupancy floor identical to measured-best config (2 blocks/SM).
// No max-subtraction needed: alpha ~ N(0,~0.8) => max over 64k ~ 3.5; exp safe.
__global__ void __launch_bounds__(512, 2)
k_fused(const float* __restrict__ Q,
        const float* __restrict__ K,
        const float* __restrict__ V,
        const float* __restrict__ w_att,
        const float* __restrict__ b_att,
        const int*   __restrict__ adj,
        const int*   __restrict__ s_mask) {
    __shared__ float wk[HH];
    __shared__ float sw0[NPC], sw1[NPC];
    __shared__ float sred[16];
    __shared__ float s_qd;
    __shared__ float4 red0[512], red1[512];

    int b = blockIdx.y, c = blockIdx.x;
    int n0 = c * NPC;
    int t = threadIdx.x;
    int w = t >> 5, l = t & 31;

    wk[t] = w_att[HH + t];

    // ---- phase 0: qdot for this b ----
    float qv = Q[b * HH + t] * w_att[t];
    qv = warp_sum(qv);
    if (l == 0) sred[w] = qv;
    __syncthreads();
    if (t == 0) {
        float s = 0.f;
#pragma unroll
        for (int i = 0; i < 16; i++) s += sred[i];
        s_qd = s + b_att[0];
    }
    __syncthreads();
    float qd = s_qd;

    // ---- phase 1: p for 128 rows (16 warps x 8 rows, batched loads then batched reductions) ----
    const float4* wk4 = (const float4*)wk;
    float4 wv0 = wk4[l], wv1 = wk4[32 + l], wv2 = wk4[64 + l], wv3 = wk4[96 + l];

    float sacc[RPW];
    const float4* kbase = (const float4*)(K + ((size_t)b * NN + n0 + w * RPW) * HH);
#pragma unroll
    for (int j = 0; j < RPW; j++) {
        const float4* kp = kbase + (size_t)j * (HH / 4);
        float4 k0 = kp[l], k1 = kp[32 + l], k2 = kp[64 + l], k3 = kp[96 + l];
        float s;
        s  = k0.x * wv0.x + k0.y * wv0.y + k0.z * wv0.z + k0.w * wv0.w;
        s += k1.x * wv1.x + k1.y * wv1.y + k1.z * wv1.z + k1.w * wv1.w;
        s += k2.x * wv2.x + k2.y * wv2.y + k2.z * wv2.z + k2.w * wv2.w;
        s += k3.x * wv3.x + k3.y * wv3.y + k3.z * wv3.z + k3.w * wv3.w;
        sacc[j] = s;
    }
#pragma unroll
    for (int j = 0; j < RPW; j++) {
        float s = warp_sum(sacc[j]);
        if (l == 0) {
            int r = w * RPW + j;
            int gi = b * NN + n0 + r;
            float p = adj[gi] ? __expf(s + qd) : 0.f;
            int smv = s_mask[gi];
            sw0[r] = smv ? p : 0.f;
            sw1[r] = smv ? 0.f : p;
            g_p[gi] = p;
        }
    }
    __syncthreads();

    // partial psum (warp 0; overlaps with start of phase 2 on other warps)
    if (w == 0) {
        float ps = 0.f;
#pragma unroll
        for (int i = 0; i < NPC / 32; i++) ps += sw0[i * 32 + l] + sw1[i * 32 + l];
        ps = warp_sum(ps);
        if (l == 0) g_psum[b * NCH + c] = ps;
    }

    // ---- phase 2: weighted V accumulation (float4, 4-way row split) ----
    int h4 = t & 127;                                  // float4 column 0..127
    int rg = t >> 7;                                   // row group 0..3
    const float4* vp = (const float4*)V + ((size_t)b * NN + n0 + rg * (NPC / 4)) * (HH / 4) + h4;
    float4 a0 = make_float4(0.f, 0.f, 0.f, 0.f);
    float4 a1 = make_float4(0.f, 0.f, 0.f, 0.f);
#pragma unroll 8
    for (int i = 0; i < NPC / 4; i++) {               // 32 rows
        float4 v = __ldg(vp + (size_t)i * (HH / 4));
        float x0 = sw0[rg * (NPC / 4) + i];
        float x1 = sw1[rg * (NPC / 4) + i];
        a0.x += x0 * v.x; a0.y += x0 * v.y; a0.z += x0 * v.z; a0.w += x0 * v.w;
        a1.x += x1 * v.x; a1.y += x1 * v.y; a1.z += x1 * v.z; a1.w += x1 * v.w;
    }
    red0[t] = a0;
    red1[t] = a1;
    __syncthreads();
    if (t < 128) {
        float4 r0 = red0[t], r1 = red1[t];
#pragma unroll
        for (int g = 1; g < 4; g++) {
            float4 x = red0[t + g * 128];
            r0.x += x.x; r0.y += x.y; r0.z += x.z; r0.w += x.w;
            float4 y = red1[t + g * 128];
            r1.x += y.x; r1.y += y.y; r1.z += y.z; r1.w += y.w;
        }
        float4* up0 = (float4*)(g_upart + ((size_t)(b * NCH + c) * 2 + 0) * HH);
        float4* up1 = (float4*)(g_upart + ((size_t)(b * NCH + c) * 2 + 1) * HH);
        up0[t] = r0;
        up1[t] = r1;
    }
}

// ---------------- normalize: u = sum(upart)/sum(p); attn = p/sum(p) ----------------
// grid (8 slices, BB), 256 threads: 256 blocks (was 32 -> SM starvation).
__global__ void __launch_bounds__(256)
k_norm(float* __restrict__ out) {
    __shared__ float sinv;
    int sl = blockIdx.x, b = blockIdx.y;
    int t = threadIdx.x, l = t & 31;

    if (t < 32) {
        float ps = (l < NCH) ? g_psum[b * NCH + l] : 0.f;
        ps = warp_sum(ps);
        if (l == 0) sinv = 1.0f / ps;
    }
    __syncthreads();
    float inv = sinv;

    // attn: slice covers 256 of 2048
    int ai = sl * 256 + t;
    out[b * NN + ai] = g_p[b * NN + ai] * inv;

    // u: first 4 slices cover 1024 = 2*HH
    if (sl < 4) {
        int ui = sl * 256 + t;
        float s = 0.f;
#pragma unroll
        for (int cc = 0; cc < NCH; cc++)
            s += g_upart[(size_t)(b * NCH + cc) * 2 * HH + ui];
        g_u[b * 2 * HH + ui] = s * inv;
    }
}

// ---------------- epilogue: attn_sum[b,o] = u0·Wr0[o] + u1·Wr1[o] + Q[b]·Wri[o] ----------------
// grid (128 o-tiles, 2 b-halves), 256 threads. Weights in smem (24KB/block);
// warp covers 2 b values with u/Q in registers. Weight DRAM traffic: once.
__global__ void __launch_bounds__(256)
k_out(const float* __restrict__ Q,
      const float* __restrict__ Wr0,
      const float* __restrict__ Wr1,
      const float* __restrict__ Wri,
      float* __restrict__ out) {
    __shared__ float s_w[3][TO][HH];
    int o0 = blockIdx.x * TO;
    int bh = blockIdx.y;
    int t = threadIdx.x, w = t >> 5, l = t & 31;

    const float4* w0g = (const float4*)(Wr0 + (size_t)o0 * HH);
    const float4* w1g = (const float4*)(Wr1 + (size_t)o0 * HH);
    const float4* wig = (const float4*)(Wri + (size_t)o0 * HH);
#pragma unroll
    for (int i = 0; i < (TO * HH / 4) / 256; i++) {
        int idx = i * 256 + t;
        ((float4*)&s_w[0][0][0])[idx] = w0g[idx];
        ((float4*)&s_w[1][0][0])[idx] = w1g[idx];
        ((float4*)&s_w[2][0][0])[idx] = wig[idx];
    }
    __syncthreads();

#pragma unroll
    for (int bb = 0; bb < 2; bb++) {
        int b = bh * 16 + bb * 8 + w;
        const float4* u0 = (const float4*)(g_u + b * 2 * HH);
        const float4* u1 = u0 + HH / 4;
        const float4* q  = (const float4*)(Q + b * HH);
        float4 u0f[4], u1f[4], qf[4];
#pragma unroll
        for (int i = 0; i < 4; i++) {
            u0f[i] = u0[i * 32 + l];
            u1f[i] = u1[i * 32 + l];
            qf[i]  = q[i * 32 + l];
        }
#pragma unroll
        for (int o = 0; o < TO; o++) {
            const float4* sw0p = (const float4*)&s_w[0][o][0];
            const float4* sw1p = (const float4*)&s_w[1][o][0];
            const float4* swip = (const float4*)&s_w[2][o][0];
            float s = 0.f;
#pragma unroll
            for (int i = 0; i < 4; i++) {
                int idx = i * 32 + l;
                float4 x;
                x = sw0p[idx];
                s += u0f[i].x * x.x + u0f[i].y * x.y + u0f[i].z * x.z + u0f[i].w * x.w;
                x = sw1p[idx];
                s += u1f[i].x * x.x + u1f[i].y * x.y + u1f[i].z * x.z + u1f[i].w * x.w;
                x = swip[idx];
                s += qf[i].x * x.x + qf[i].y * x.y + qf[i].z * x.z + qf[i].w * x.w;
            }
            s = warp_sum(s);
            if (l == 0) out[BB * NN + b * HH + o0 + o] = s;
        }
    }
}

// ---------------- launch ----------------
extern "C" void kernel_launch(void* const* d_in, const int* in_sizes, int n_in,
                              void* d_out, int out_size) {
    const float* Q     = (const float*)d_in[0];
    const float* K     = (const float*)d_in[1];
    const float* V     = (const float*)d_in[2];
    const int*   adj   = (const int*)d_in[3];
    const int*   smask = (const int*)d_in[4];
    const float* w_att = (const float*)d_in[5];
    const float* b_att = (const float*)d_in[6];
    const float* Wr0   = (const float*)d_in[7];
    const float* Wr1   = (const float*)d_in[8];
    const float* Wri   = (const float*)d_in[9];
    float* out = (float*)d_out;

    k_fused<<<dim3(NCH, BB), 512>>>(Q, K, V, w_att, b_att, adj, smask);
    k_norm<<<dim3(8, BB), 256>>>(out);
    k_out<<<dim3(HH / TO, 2), 256>>>(Q, Wr0, Wr1, Wri, out);
}